// round 8
// baseline (speedup 1.0000x reference)
#include <cuda_runtime.h>
#include <cuda_fp16.h>
#include <stdint.h>

// ---------------------------------------------------------------------------
// StyleGAN2 modulated 3x3 conv, NHWC, N=16 H=W=64 C=O=512
// Round 8: single-product fp16 mma.sync. Warp tile 64x64 (128B smem/MMA,
//          -33% vs R7) -- CTA 128x128 with 4 warps / 128 threads,
//          kc=64, 3-stage cp.async pipeline, 2 CTAs/SM.
// ---------------------------------------------------------------------------

#define NN 16
#define HH 64
#define WW 64
#define CC 512
#define OO 512
#define NWD 14

#define STAGE_BYTES 32768   // A 16K | B 16K
#define OFF_B  16384
#define NCHUNK 72           // 9 taps x 8 c-chunks (kc=64)

// ---- device scratch (allocation-free) --------------------------------------
__device__ float g_s[NN * CC];
__device__ float g_dmul[NN * OO];
__device__ float g_ssq[CC * OO];
__device__ __half g_xh[NN * HH * WW * CC];   // fp16(x*s)
__device__ __half g_wt[9 * OO * CC];         // fp16 w^T [tap][o][c]

// ---- helpers -----------------------------------------------------------------
static __device__ __forceinline__ uint32_t smem_u32(const void* p) {
    uint32_t a;
    asm("{ .reg .u64 t; cvta.to.shared.u64 t, %1; cvt.u32.u64 %0, t; }"
        : "=r"(a) : "l"(p));
    return a;
}

#define CP16(dst, src, sz)                                                   \
    asm volatile("cp.async.cg.shared.global [%0], [%1], 16, %2;"             \
                 :: "r"(dst), "l"(src), "r"(sz) : "memory")
#define CP_COMMIT() asm volatile("cp.async.commit_group;" ::: "memory")
#define CP_WAIT1()  asm volatile("cp.async.wait_group 1;" ::: "memory")
#define CP_WAIT0()  asm volatile("cp.async.wait_group 0;" ::: "memory")

#define LDSM4(r, addr)                                                       \
    asm volatile("ldmatrix.sync.aligned.m8n8.x4.shared.b16 "                 \
                 "{%0,%1,%2,%3}, [%4];"                                      \
                 : "=r"((r)[0]), "=r"((r)[1]), "=r"((r)[2]), "=r"((r)[3])    \
                 : "r"(addr))

#define MMA2(d, a, b0, b1)                                                   \
    asm volatile("mma.sync.aligned.m16n8k16.row.col.f32.f16.f16.f32 "        \
                 "{%0,%1,%2,%3}, {%4,%5,%6,%7}, {%8,%9}, {%0,%1,%2,%3};"     \
                 : "+f"((d)[0]), "+f"((d)[1]), "+f"((d)[2]), "+f"((d)[3])    \
                 : "r"((a)[0]), "r"((a)[1]), "r"((a)[2]), "r"((a)[3]),       \
                   "r"(b0), "r"(b1))

// 128B rows, 8x16B chunks, XOR swizzle by row&7 (conflict-free ldmatrix)
#define SWZ128(row, ch) (((row) * 128) + ((((ch) ^ ((row) & 7))) << 4))

// ---- prep 1: style (blocks 0..15) + ssq (blocks 16..527) ----------------------
__global__ void prep1_kernel(const float* __restrict__ dlat,
                             const float* __restrict__ sw,
                             const float* __restrict__ sb,
                             const int*   __restrict__ lidx,
                             const float* __restrict__ weight)
{
    int bid = blockIdx.x;
    int t = threadIdx.x;
    if (bid < NN) {
        int n = bid;
        __shared__ float dl[CC];
        int li = *lidx;
        dl[t] = dlat[(n * NWD + li) * CC + t];
        __syncthreads();
        float acc = 0.f;
#pragma unroll 4
        for (int w = 0; w < CC; ++w)
            acc += dl[w] * sw[w * CC + t];
        g_s[n * CC + t] = acc * 0.044194173824159216f + sb[t];
    } else {
        int i = bid - NN;
        float acc = 0.f;
#pragma unroll
        for (int tp = 0; tp < 9; ++tp) {
            float v = weight[(tp * CC + i) * OO + t];
            acc += v * v;
        }
        g_ssq[i * OO + t] = acc;
    }
}

// ---- prep 2: dmul[n,o] ---------------------------------------------------------
__global__ void dmul_kernel()
{
    int n = blockIdx.x;
    int o = threadIdx.x;
    __shared__ float s2[CC];
    float sv = g_s[n * CC + o];
    s2[o] = sv * sv;
    __syncthreads();
    float acc = 0.f;
#pragma unroll 4
    for (int i = 0; i < CC; ++i)
        acc += s2[i] * g_ssq[i * OO + o];
    const float ws2 = 1.0f / 4608.0f;
    const float ws  = 0.014731391274719738f;
    g_dmul[n * OO + o] = ws * rsqrtf(ws2 * acc + 1e-8f);
}

// ---- prep 3: x*s -> fp16 (blocks < 32768) + w transpose fp16 (rest) -------------
__global__ void prep3_kernel(const float* __restrict__ x,
                             const float* __restrict__ weight)
{
    int bid = blockIdx.x;
    int tid = threadIdx.x;
    if (bid < 32768) {
        int t = bid * 256 + tid;
        int e = t * 4;
        int c = e & (CC - 1);
        int n = e >> 21;
        float4 v = *(const float4*)(x + e);
        float4 s = *(const float4*)(g_s + n * CC + c);
        __half h0 = __float2half_rn(v.x * s.x);
        __half h1 = __float2half_rn(v.y * s.y);
        __half h2 = __float2half_rn(v.z * s.z);
        __half h3 = __float2half_rn(v.w * s.w);
        uint2 ph;
        ph.x = (uint32_t)__half_as_ushort(h0) | ((uint32_t)__half_as_ushort(h1) << 16);
        ph.y = (uint32_t)__half_as_ushort(h2) | ((uint32_t)__half_as_ushort(h3) << 16);
        *(uint2*)(g_xh + e) = ph;
    } else {
        __shared__ float ts[32][33];
        int wb = bid - 32768;            // 0..2303
        int tap = wb >> 8;
        int rem = wb & 255;
        int o0 = (rem & 15) * 32;
        int c0 = (rem >> 4) * 32;
        int tx = tid & 31, ty = tid >> 5;
        for (int j = ty; j < 32; j += 8)
            ts[j][tx] = weight[(tap * CC + c0 + j) * OO + o0 + tx];
        __syncthreads();
        for (int j = ty; j < 32; j += 8) {
            float v = ts[tx][j];
            int oi = (tap * OO + o0 + j) * CC + c0 + tx;
            g_wt[oi] = __float2half_rn(v);
        }
    }
}

// ---- chunk staging via cp.async (128 threads, 16x16B each) ----------------------
static __device__ __forceinline__ void load_chunk(uint32_t sb, int ci,
                                                  int n, int h0, int o0, int tid)
{
    const int tap = ci >> 3;              // 0..8
    const int c0  = (ci & 7) * 64;        // kc=64
    const int dy  = tap / 3 - 1;
    const int dx  = tap % 3 - 1;
    const int r   = tid;                  // 0..127: one full 128B row each
    const int r7  = r & 7;

    // ---- A row (spatial, tap-shifted, zero-filled halo)
    int hs = h0 + (r >> 6) + dy;
    int ws = (r & 63) + dx;
    const bool ok = ((unsigned)hs < (unsigned)HH) && ((unsigned)ws < (unsigned)WW);
    const unsigned szA = ok ? 16u : 0u;
    const int hc = ok ? hs : 0;
    const int wc = ok ? ws : 0;
    const size_t aidx = ((size_t)((n * HH + hc) * WW + wc) * CC + c0) * 2;
    const char* srcA = (const char*)g_xh + aidx;
#pragma unroll
    for (int c = 0; c < 8; ++c) {
        uint32_t d = sb + r * 128 + ((c ^ r7) << 4);
        CP16(d, srcA + c * 16, szA);
    }

    // ---- B row (one o-channel)
    const size_t bidx = ((size_t)((tap * OO + o0 + r) * CC) + c0) * 2;
    const char* srcB = (const char*)g_wt + bidx;
#pragma unroll
    for (int c = 0; c < 8; ++c) {
        uint32_t d = sb + OFF_B + r * 128 + ((c ^ r7) << 4);
        CP16(d, srcB + c * 16, 16u);
    }
}

// ---- kernel 4: main conv on mma.sync (4 warps, warp tile 64x64) ------------------
__global__ __launch_bounds__(128, 2)
void conv_mma_kernel(const float* __restrict__ bias,
                     const float* __restrict__ nstr,
                     const float* __restrict__ noise,
                     float* __restrict__ out)
{
    extern __shared__ char dynsmem[];
    const uint32_t smbase = smem_u32(dynsmem);

    const int tid  = threadIdx.x;
    const int lane = tid & 31;
    const int wid  = tid >> 5;
    const int wm   = wid & 1;          // M half (64 rows)
    const int wn   = wid >> 1;         // N half (64 cols)

    const int o0 = blockIdx.x * 128;
    const int mt = blockIdx.y;
    const int n  = mt >> 5;
    const int h0 = (mt & 31) * 2;

    // ldmatrix lane mappings
    const int a_row  = wm * 64 + (lane & 15);            // + mi*16
    const int a_kh   = lane >> 4;
    const int bg     = lane >> 3;
    const int b_row0 = wn * 64 + ((bg >> 1) << 3) + (lane & 7);  // + nb*16
    const int b_kh   = bg & 1;

    float acc[4][8][4];
#pragma unroll
    for (int mi = 0; mi < 4; ++mi)
#pragma unroll
        for (int ni = 0; ni < 8; ++ni)
#pragma unroll
            for (int q = 0; q < 4; ++q) acc[mi][ni][q] = 0.f;

    // 3-stage pipeline prologue: chunks 0 and 1 in flight
    load_chunk(smbase, 0, n, h0, o0, tid); CP_COMMIT();
    load_chunk(smbase + STAGE_BYTES, 1, n, h0, o0, tid); CP_COMMIT();

    int s_cur = 0;
    for (int i = 0; i < NCHUNK; ++i) {
        if (i + 1 < NCHUNK) CP_WAIT1(); else CP_WAIT0();  // chunk i resident
        __syncthreads();                  // visible to all; all done with i-1
        if (i + 2 < NCHUNK) {             // prefetch i+2 into stage compute(i-1) used
            int s_nxt = s_cur + 2; if (s_nxt >= 3) s_nxt -= 3;
            load_chunk(smbase + s_nxt * STAGE_BYTES, i + 2, n, h0, o0, tid);
            CP_COMMIT();
        }

        const uint32_t sb = smbase + s_cur * STAGE_BYTES;
#pragma unroll
        for (int k16 = 0; k16 < 4; ++k16) {
            const int cha = 2 * k16 + a_kh;
            const int chb = 2 * k16 + b_kh;
            uint32_t aa[4][4], bb[4][4];
#pragma unroll
            for (int mi = 0; mi < 4; ++mi)
                LDSM4(aa[mi], sb + SWZ128(a_row + mi * 16, cha));
#pragma unroll
            for (int nb = 0; nb < 4; ++nb)
                LDSM4(bb[nb], sb + OFF_B + SWZ128(b_row0 + nb * 16, chb));
#pragma unroll
            for (int mi = 0; mi < 4; ++mi)
#pragma unroll
                for (int nb = 0; nb < 4; ++nb) {
                    MMA2(acc[mi][2*nb],   aa[mi], bb[nb][0], bb[nb][1]);
                    MMA2(acc[mi][2*nb+1], aa[mi], bb[nb][2], bb[nb][3]);
                }
        }
        ++s_cur; if (s_cur >= 3) s_cur = 0;
    }

    // ---- epilogue: demod, noise, bias, leaky_relu * sqrt(2)
    const float nstrv = *nstr;
#pragma unroll
    for (int mi = 0; mi < 4; ++mi) {
#pragma unroll
        for (int half = 0; half < 2; ++half) {
            int m = wm * 64 + mi * 16 + (lane >> 2) + half * 8;
            int h = h0 + (m >> 6);
            int w = m & 63;
            float nz = noise[(n * HH + h) * WW + w] * nstrv;
            size_t base = ((size_t)((n * HH + h) * WW + w)) * OO + o0;
#pragma unroll
            for (int ni = 0; ni < 8; ++ni) {
                int oc = wn * 64 + ni * 8 + 2 * (lane & 3);
                float dm0 = g_dmul[n * OO + o0 + oc];
                float dm1 = g_dmul[n * OO + o0 + oc + 1];
                float b0 = bias[o0 + oc], b1 = bias[o0 + oc + 1];
                float y0 = fmaf(acc[mi][ni][half * 2],     dm0, nz + b0);
                float y1 = fmaf(acc[mi][ni][half * 2 + 1], dm1, nz + b1);
                y0 = (y0 > 0.f ? y0 : 0.2f * y0) * 1.4142135623730951f;
                y1 = (y1 > 0.f ? y1 : 0.2f * y1) * 1.4142135623730951f;
                *(float2*)(out + base + oc) = make_float2(y0, y1);
            }
        }
    }
}

// ---------------------------------------------------------------------------
extern "C" void kernel_launch(void* const* d_in, const int* in_sizes, int n_in,
                              void* d_out, int out_size)
{
    const float* x      = (const float*)d_in[0];
    const float* dlat   = (const float*)d_in[1];
    const float* sw     = (const float*)d_in[2];
    const float* sbv    = (const float*)d_in[3];
    const float* weight = (const float*)d_in[4];
    const float* bias   = (const float*)d_in[5];
    const float* nstr   = (const float*)d_in[6];
    const float* noise  = (const float*)d_in[7];
    const int*   lidx   = (const int*)  d_in[8];
    float* out = (float*)d_out;

    prep1_kernel<<<NN + CC, 512>>>(dlat, sw, sbv, lidx, weight);
    dmul_kernel<<<NN, 512>>>();
    prep3_kernel<<<32768 + 2304, 256>>>(x, weight);

    const int smem_bytes = 3 * STAGE_BYTES;   // 98304 per CTA (2 CTAs/SM)
    cudaFuncSetAttribute(conv_mma_kernel,
                         cudaFuncAttributeMaxDynamicSharedMemorySize, smem_bytes);
    conv_mma_kernel<<<dim3(4, 512), 128, smem_bytes>>>(bias, nstr, noise, out);
}

// round 9
// speedup vs baseline: 1.3481x; 1.3481x over previous
#include <cuda_runtime.h>
#include <cuda_fp16.h>
#include <stdint.h>

// ---------------------------------------------------------------------------
// StyleGAN2 modulated 3x3 conv, NHWC, N=16 H=W=64 C=O=512
// Round 9: R7 config (CTA 128x128, warp 32x64, kc=64, 3-stage cp.async,
//          2 CTAs/SM, single-product fp16) + register double-buffered
//          fragments: LDSM(k16+1) issued before MMA(k16) so crossbar and
//          tensor pipe overlap instead of serializing.
// ---------------------------------------------------------------------------

#define NN 16
#define HH 64
#define WW 64
#define CC 512
#define OO 512
#define NWD 14

#define STAGE_BYTES 32768   // A 16K | B 16K
#define OFF_B  16384
#define NCHUNK 72           // 9 taps x 8 c-chunks (kc=64)

// ---- device scratch (allocation-free) --------------------------------------
__device__ float g_s[NN * CC];
__device__ float g_dmul[NN * OO];
__device__ float g_ssq[CC * OO];
__device__ __half g_xh[NN * HH * WW * CC];   // fp16(x*s)
__device__ __half g_wt[9 * OO * CC];         // fp16 w^T [tap][o][c]

// ---- helpers -----------------------------------------------------------------
static __device__ __forceinline__ uint32_t smem_u32(const void* p) {
    uint32_t a;
    asm("{ .reg .u64 t; cvta.to.shared.u64 t, %1; cvt.u32.u64 %0, t; }"
        : "=r"(a) : "l"(p));
    return a;
}

#define CP16(dst, src, sz)                                                   \
    asm volatile("cp.async.cg.shared.global [%0], [%1], 16, %2;"             \
                 :: "r"(dst), "l"(src), "r"(sz) : "memory")
#define CP_COMMIT() asm volatile("cp.async.commit_group;" ::: "memory")
#define CP_WAIT1()  asm volatile("cp.async.wait_group 1;" ::: "memory")
#define CP_WAIT0()  asm volatile("cp.async.wait_group 0;" ::: "memory")

#define LDSM4(r, addr)                                                       \
    asm volatile("ldmatrix.sync.aligned.m8n8.x4.shared.b16 "                 \
                 "{%0,%1,%2,%3}, [%4];"                                      \
                 : "=r"((r)[0]), "=r"((r)[1]), "=r"((r)[2]), "=r"((r)[3])    \
                 : "r"(addr))

#define MMA2(d, a, b0, b1)                                                   \
    asm volatile("mma.sync.aligned.m16n8k16.row.col.f32.f16.f16.f32 "        \
                 "{%0,%1,%2,%3}, {%4,%5,%6,%7}, {%8,%9}, {%0,%1,%2,%3};"     \
                 : "+f"((d)[0]), "+f"((d)[1]), "+f"((d)[2]), "+f"((d)[3])    \
                 : "r"((a)[0]), "r"((a)[1]), "r"((a)[2]), "r"((a)[3]),       \
                   "r"(b0), "r"(b1))

// 128B rows, 8x16B chunks, XOR swizzle by row&7 (conflict-free ldmatrix)
#define SWZ128(row, ch) (((row) * 128) + ((((ch) ^ ((row) & 7))) << 4))

// ---- prep 1: style (blocks 0..15) + ssq (blocks 16..527) ----------------------
__global__ void prep1_kernel(const float* __restrict__ dlat,
                             const float* __restrict__ sw,
                             const float* __restrict__ sb,
                             const int*   __restrict__ lidx,
                             const float* __restrict__ weight)
{
    int bid = blockIdx.x;
    int t = threadIdx.x;
    if (bid < NN) {
        int n = bid;
        __shared__ float dl[CC];
        int li = *lidx;
        dl[t] = dlat[(n * NWD + li) * CC + t];
        __syncthreads();
        float acc = 0.f;
#pragma unroll 4
        for (int w = 0; w < CC; ++w)
            acc += dl[w] * sw[w * CC + t];
        g_s[n * CC + t] = acc * 0.044194173824159216f + sb[t];
    } else {
        int i = bid - NN;
        float acc = 0.f;
#pragma unroll
        for (int tp = 0; tp < 9; ++tp) {
            float v = weight[(tp * CC + i) * OO + t];
            acc += v * v;
        }
        g_ssq[i * OO + t] = acc;
    }
}

// ---- prep 2: dmul[n,o] ---------------------------------------------------------
__global__ void dmul_kernel()
{
    int n = blockIdx.x;
    int o = threadIdx.x;
    __shared__ float s2[CC];
    float sv = g_s[n * CC + o];
    s2[o] = sv * sv;
    __syncthreads();
    float acc = 0.f;
#pragma unroll 4
    for (int i = 0; i < CC; ++i)
        acc += s2[i] * g_ssq[i * OO + o];
    const float ws2 = 1.0f / 4608.0f;
    const float ws  = 0.014731391274719738f;
    g_dmul[n * OO + o] = ws * rsqrtf(ws2 * acc + 1e-8f);
}

// ---- prep 3: x*s -> fp16 (blocks < 32768) + w transpose fp16 (rest) -------------
__global__ void prep3_kernel(const float* __restrict__ x,
                             const float* __restrict__ weight)
{
    int bid = blockIdx.x;
    int tid = threadIdx.x;
    if (bid < 32768) {
        int t = bid * 256 + tid;
        int e = t * 4;
        int c = e & (CC - 1);
        int n = e >> 21;
        float4 v = *(const float4*)(x + e);
        float4 s = *(const float4*)(g_s + n * CC + c);
        __half h0 = __float2half_rn(v.x * s.x);
        __half h1 = __float2half_rn(v.y * s.y);
        __half h2 = __float2half_rn(v.z * s.z);
        __half h3 = __float2half_rn(v.w * s.w);
        uint2 ph;
        ph.x = (uint32_t)__half_as_ushort(h0) | ((uint32_t)__half_as_ushort(h1) << 16);
        ph.y = (uint32_t)__half_as_ushort(h2) | ((uint32_t)__half_as_ushort(h3) << 16);
        *(uint2*)(g_xh + e) = ph;
    } else {
        __shared__ float ts[32][33];
        int wb = bid - 32768;            // 0..2303
        int tap = wb >> 8;
        int rem = wb & 255;
        int o0 = (rem & 15) * 32;
        int c0 = (rem >> 4) * 32;
        int tx = tid & 31, ty = tid >> 5;
        for (int j = ty; j < 32; j += 8)
            ts[j][tx] = weight[(tap * CC + c0 + j) * OO + o0 + tx];
        __syncthreads();
        for (int j = ty; j < 32; j += 8) {
            float v = ts[tx][j];
            int oi = (tap * OO + o0 + j) * CC + c0 + tx;
            g_wt[oi] = __float2half_rn(v);
        }
    }
}

// ---- chunk staging via cp.async (256 threads, 8x16B each) -----------------------
static __device__ __forceinline__ void load_chunk(uint32_t sb, int ci,
                                                  int n, int h0, int o0, int tid)
{
    const int tap = ci >> 3;              // 0..8
    const int c0  = (ci & 7) * 64;        // kc=64
    const int dy  = tap / 3 - 1;
    const int dx  = tap % 3 - 1;
    const int r   = tid >> 1;             // 0..127
    const int cb  = (tid & 1) * 4;        // 4 consecutive 16B chunks
    const int r7  = r & 7;

    // ---- A rows (128 spatial, tap-shifted, zero-filled halo)
    int hs = h0 + (r >> 6) + dy;
    int ws = (r & 63) + dx;
    const bool ok = ((unsigned)hs < (unsigned)HH) && ((unsigned)ws < (unsigned)WW);
    const unsigned szA = ok ? 16u : 0u;
    const int hc = ok ? hs : 0;
    const int wc = ok ? ws : 0;
    const size_t aidx = ((size_t)((n * HH + hc) * WW + wc) * CC + c0 + cb * 8) * 2;
    const char* srcA = (const char*)g_xh + aidx;
#pragma unroll
    for (int c = 0; c < 4; ++c) {
        uint32_t d = sb + r * 128 + (((cb + c) ^ r7) << 4);
        CP16(d, srcA + c * 16, szA);
    }

    // ---- B rows (128 o-channels)
    const size_t bidx = ((size_t)((tap * OO + o0 + r) * CC) + c0 + cb * 8) * 2;
    const char* srcB = (const char*)g_wt + bidx;
#pragma unroll
    for (int c = 0; c < 4; ++c) {
        uint32_t d = sb + OFF_B + r * 128 + (((cb + c) ^ r7) << 4);
        CP16(d, srcB + c * 16, 16u);
    }
}

// ---- kernel 4: main conv on mma.sync, reg double-buffered fragments --------------
__global__ __launch_bounds__(256, 2)
void conv_mma_kernel(const float* __restrict__ bias,
                     const float* __restrict__ nstr,
                     const float* __restrict__ noise,
                     float* __restrict__ out)
{
    extern __shared__ char dynsmem[];
    const uint32_t smbase = smem_u32(dynsmem);

    const int tid  = threadIdx.x;
    const int lane = tid & 31;
    const int wid  = tid >> 5;
    const int wm   = wid & 3;          // M quarter (32 rows)
    const int wn   = wid >> 2;         // N half (64 cols)

    const int o0 = blockIdx.x * 128;
    const int mt = blockIdx.y;
    const int n  = mt >> 5;
    const int h0 = (mt & 31) * 2;

    // ldmatrix lane mappings
    const int a_row  = wm * 32 + (lane & 15);            // + mi*16
    const int a_kh   = lane >> 4;
    const int bg     = lane >> 3;
    const int b_row0 = wn * 64 + ((bg >> 1) << 3) + (lane & 7);  // + nb*16
    const int b_kh   = bg & 1;

    // per-warp row base offsets (row*128 part of SWZ128), hoisted
    const uint32_t aro0 = (uint32_t)(a_row) * 128u;
    const uint32_t aro1 = (uint32_t)(a_row + 16) * 128u;
    const uint32_t ar7_0 = (a_row) & 7, ar7_1 = (a_row + 16) & 7;
    uint32_t bro[4], br7[4];
#pragma unroll
    for (int nb = 0; nb < 4; ++nb) {
        bro[nb] = (uint32_t)(b_row0 + nb * 16) * 128u + OFF_B;
        br7[nb] = (b_row0 + nb * 16) & 7;
    }

    float acc[2][8][4];
#pragma unroll
    for (int mi = 0; mi < 2; ++mi)
#pragma unroll
        for (int ni = 0; ni < 8; ++ni)
#pragma unroll
            for (int q = 0; q < 4; ++q) acc[mi][ni][q] = 0.f;

    // 3-stage pipeline prologue: chunks 0 and 1 in flight
    load_chunk(smbase, 0, n, h0, o0, tid); CP_COMMIT();
    load_chunk(smbase + STAGE_BYTES, 1, n, h0, o0, tid); CP_COMMIT();

    int s_cur = 0;
    for (int i = 0; i < NCHUNK; ++i) {
        if (i + 1 < NCHUNK) CP_WAIT1(); else CP_WAIT0();  // chunk i resident
        __syncthreads();                  // visible to all; all done with i-1
        if (i + 2 < NCHUNK) {             // prefetch i+2 into stage compute(i-1) used
            int s_nxt = s_cur + 2; if (s_nxt >= 3) s_nxt -= 3;
            load_chunk(smbase + s_nxt * STAGE_BYTES, i + 2, n, h0, o0, tid);
            CP_COMMIT();
        }

        const uint32_t sb = smbase + s_cur * STAGE_BYTES;

        // double-buffered fragments: buf = k16 & 1
        uint32_t fa[2][2][4], fb[2][4][4];

        // prime k16=0 into buffer 0
        LDSM4(fa[0][0], sb + aro0 + (((unsigned)a_kh ^ ar7_0) << 4));
        LDSM4(fa[0][1], sb + aro1 + (((unsigned)a_kh ^ ar7_1) << 4));
#pragma unroll
        for (int nb = 0; nb < 4; ++nb)
            LDSM4(fb[0][nb], sb + bro[nb] + (((unsigned)b_kh ^ br7[nb]) << 4));

#pragma unroll
        for (int k16 = 0; k16 < 4; ++k16) {
            const int cur = k16 & 1;
            const int nxt = cur ^ 1;
            if (k16 < 3) {
                // issue next k16's LDSM before this k16's MMAs (overlap)
                const unsigned cha = 2 * (k16 + 1) + a_kh;
                const unsigned chb = 2 * (k16 + 1) + b_kh;
                LDSM4(fa[nxt][0], sb + aro0 + ((cha ^ ar7_0) << 4));
                LDSM4(fa[nxt][1], sb + aro1 + ((cha ^ ar7_1) << 4));
#pragma unroll
                for (int nb = 0; nb < 4; ++nb)
                    LDSM4(fb[nxt][nb], sb + bro[nb] + ((chb ^ br7[nb]) << 4));
            }
#pragma unroll
            for (int mi = 0; mi < 2; ++mi)
#pragma unroll
                for (int nb = 0; nb < 4; ++nb) {
                    MMA2(acc[mi][2*nb],   fa[cur][mi], fb[cur][nb][0], fb[cur][nb][1]);
                    MMA2(acc[mi][2*nb+1], fa[cur][mi], fb[cur][nb][2], fb[cur][nb][3]);
                }
        }
        ++s_cur; if (s_cur >= 3) s_cur = 0;
    }

    // ---- epilogue: demod, noise, bias, leaky_relu * sqrt(2)
    const float nstrv = *nstr;
#pragma unroll
    for (int mi = 0; mi < 2; ++mi) {
#pragma unroll
        for (int half = 0; half < 2; ++half) {
            int m = wm * 32 + mi * 16 + (lane >> 2) + half * 8;
            int h = h0 + (m >> 6);
            int w = m & 63;
            float nz = noise[(n * HH + h) * WW + w] * nstrv;
            size_t base = ((size_t)((n * HH + h) * WW + w)) * OO + o0;
#pragma unroll
            for (int ni = 0; ni < 8; ++ni) {
                int oc = wn * 64 + ni * 8 + 2 * (lane & 3);
                float dm0 = g_dmul[n * OO + o0 + oc];
                float dm1 = g_dmul[n * OO + o0 + oc + 1];
                float b0 = bias[o0 + oc], b1 = bias[o0 + oc + 1];
                float y0 = fmaf(acc[mi][ni][half * 2],     dm0, nz + b0);
                float y1 = fmaf(acc[mi][ni][half * 2 + 1], dm1, nz + b1);
                y0 = (y0 > 0.f ? y0 : 0.2f * y0) * 1.4142135623730951f;
                y1 = (y1 > 0.f ? y1 : 0.2f * y1) * 1.4142135623730951f;
                *(float2*)(out + base + oc) = make_float2(y0, y1);
            }
        }
    }
}

// ---------------------------------------------------------------------------
extern "C" void kernel_launch(void* const* d_in, const int* in_sizes, int n_in,
                              void* d_out, int out_size)
{
    const float* x      = (const float*)d_in[0];
    const float* dlat   = (const float*)d_in[1];
    const float* sw     = (const float*)d_in[2];
    const float* sbv    = (const float*)d_in[3];
    const float* weight = (const float*)d_in[4];
    const float* bias   = (const float*)d_in[5];
    const float* nstr   = (const float*)d_in[6];
    const float* noise  = (const float*)d_in[7];
    const int*   lidx   = (const int*)  d_in[8];
    float* out = (float*)d_out;

    prep1_kernel<<<NN + CC, 512>>>(dlat, sw, sbv, lidx, weight);
    dmul_kernel<<<NN, 512>>>();
    prep3_kernel<<<32768 + 2304, 256>>>(x, weight);

    const int smem_bytes = 3 * STAGE_BYTES;   // 98304 per CTA (2 CTAs/SM)
    cudaFuncSetAttribute(conv_mma_kernel,
                         cudaFuncAttributeMaxDynamicSharedMemorySize, smem_bytes);
    conv_mma_kernel<<<dim3(4, 512), 256, smem_bytes>>>(bias, nstr, noise, out);
}